// round 3
// baseline (speedup 1.0000x reference)
#include <cuda_runtime.h>
#include <cuda_bf16.h>
#include <math_constants.h>

#define N_S   50000
#define N_P   10000
#define EN    320000
#define D_IN  512
#define D_OUT 256
#define M_PAD 10112   // 79 * 128

// ---------------- scratch (static device globals; no allocation) ----------------
__device__ __align__(16) float g_w1[D_IN];
__device__ __align__(16) float g_w2[D_IN];
__device__ float g_s_src[N_S];
__device__ float g_s_dst[N_P];
__device__ int   g_cnt[N_P];
__device__ int   g_off[N_P + 1];
__device__ int   g_cur[N_P];
__device__ int   g_src_csr[EN];
__device__ float g_alpha[EN];
// aggregated h per dst, bf16 hi/lo split (rows >= N_P stay zero)
__device__ __align__(16) __nv_bfloat16 g_agg_hi[(size_t)M_PAD * D_IN];
__device__ __align__(16) __nv_bfloat16 g_agg_lo[(size_t)M_PAD * D_IN];
// W in bf16 hi/lo split
__device__ __align__(16) __nv_bfloat16 g_W_hi[(size_t)D_OUT * D_IN];
__device__ __align__(16) __nv_bfloat16 g_W_lo[(size_t)D_OUT * D_IN];

__device__ __forceinline__ unsigned short bf_bits(__nv_bfloat16 h) {
    return *reinterpret_cast<unsigned short*>(&h);
}

// ---------------- K0: zero per-dst edge counts ----------------
__global__ void k_zero_cnt() {
    int i = blockIdx.x * blockDim.x + threadIdx.x;
    if (i < N_P) g_cnt[i] = 0;
}

// ---------------- K1: fold attention vector through W ----------------
__global__ void k_fold_w(const float* __restrict__ W, const float* __restrict__ aw) {
    int k = blockIdx.x * 32 + threadIdx.x;   // 16 blocks x 32 threads
    float a1 = 0.f, a2 = 0.f;
    #pragma unroll 8
    for (int d = 0; d < D_OUT; d++) {
        float w = W[d * D_IN + k];
        a1 += w * aw[d];
        a2 += w * aw[D_OUT + d];
    }
    g_w1[k] = a1;
    g_w2[k] = a2;
}

// ---------------- K1b: split W into bf16 hi/lo ----------------
__global__ void k_convw(const float* __restrict__ W) {
    int i = blockIdx.x * blockDim.x + threadIdx.x;
    float v = W[i];
    __nv_bfloat16 hi = __float2bfloat16_rn(v);
    float r = v - __bfloat162float(hi);
    g_W_hi[i] = hi;
    g_W_lo[i] = __float2bfloat16_rn(r);
}

// ---------------- K2: per-node scalar scores (warp per row) ----------------
__global__ void k_scores(const float* __restrict__ hs, const float* __restrict__ hp) {
    int gw   = (blockIdx.x * blockDim.x + threadIdx.x) >> 5;
    int lane = threadIdx.x & 31;
    if (gw >= N_S + N_P) return;
    float acc = 0.f;
    if (gw < N_S) {
        const float4* row = (const float4*)(hs + (size_t)gw * D_IN);
        const float4* wv  = (const float4*)g_w1;
        #pragma unroll
        for (int i = lane; i < D_IN / 4; i += 32) {
            float4 a = __ldg(row + i);      // default policy: keep h_s in L2 for aggregate
            float4 b = wv[i];
            acc += a.x * b.x + a.y * b.y + a.z * b.z + a.w * b.w;
        }
    } else {
        const float4* row = (const float4*)(hp + (size_t)(gw - N_S) * D_IN);
        const float4* wv  = (const float4*)g_w2;
        #pragma unroll
        for (int i = lane; i < D_IN / 4; i += 32) {
            float4 a = __ldcs(row + i);     // streaming: h_p never reused
            float4 b = wv[i];
            acc += a.x * b.x + a.y * b.y + a.z * b.z + a.w * b.w;
        }
    }
    #pragma unroll
    for (int o = 16; o; o >>= 1) acc += __shfl_xor_sync(0xffffffffu, acc, o);
    if (lane == 0) {
        if (gw < N_S) g_s_src[gw] = acc;
        else          g_s_dst[gw - N_S] = acc;
    }
}

// ---------------- K3: dst histogram only ----------------
__global__ void k_count(const int* __restrict__ dst) {
    int e = blockIdx.x * blockDim.x + threadIdx.x;
    if (e >= EN) return;
    atomicAdd(&g_cnt[dst[e]], 1);
}

// ---------------- K4: exclusive scan of counts -> CSR offsets ----------------
__global__ void k_scan() {
    __shared__ int wsum[32];
    int t    = threadIdx.x;
    int lane = t & 31;
    int wid  = t >> 5;
    int base = t * 10;
    int incl_loc[10];
    int cnts[10];
    int tot = 0;
    if (t < 1000) {
        #pragma unroll
        for (int i = 0; i < 10; i++) {
            int c = g_cnt[base + i];
            cnts[i] = c;
            tot += c;
            incl_loc[i] = tot;
        }
    }
    int incl = tot;
    #pragma unroll
    for (int o = 1; o < 32; o <<= 1) {
        int v = __shfl_up_sync(0xffffffffu, incl, o);
        if (lane >= o) incl += v;
    }
    if (lane == 31) wsum[wid] = incl;
    __syncthreads();
    if (wid == 0) {
        int v = wsum[lane];
        #pragma unroll
        for (int o = 1; o < 32; o <<= 1) {
            int u = __shfl_up_sync(0xffffffffu, v, o);
            if (lane >= o) v += u;
        }
        wsum[lane] = v;
    }
    __syncthreads();
    int warpoff = (wid == 0) ? 0 : wsum[wid - 1];
    int texcl   = warpoff + incl - tot;
    if (t < 1000) {
        #pragma unroll
        for (int i = 0; i < 10; i++) {
            int iv = texcl + incl_loc[i];
            g_off[base + i + 1] = iv;
            g_cur[base + i]     = iv - cnts[i];
        }
    }
    if (t == 0) g_off[0] = 0;
}

// ---------------- K5: scatter src ids into CSR order ----------------
__global__ void k_scatter(const int* __restrict__ src, const int* __restrict__ dst) {
    int e = blockIdx.x * blockDim.x + threadIdx.x;
    if (e >= EN) return;
    int pos = atomicAdd(&g_cur[dst[e]], 1);
    g_src_csr[pos] = src[e];
}

// ---------------- K6: warp-per-dst softmax -> alpha in CSR order ----------------
__global__ void k_softmax() {
    int p    = (blockIdx.x * blockDim.x + threadIdx.x) >> 5;
    int lane = threadIdx.x & 31;
    if (p >= N_P) return;
    int start = g_off[p];
    int cnt   = g_off[p + 1] - start;
    float sd  = g_s_dst[p];

    // pass 1: max of leaky(s_src + s_dst)
    float m = -CUDART_INF_F;
    for (int j = lane; j < cnt; j += 32) {
        float v = g_s_src[g_src_csr[start + j]] + sd;
        v = (v > 0.f) ? v : 0.01f * v;
        m = fmaxf(m, v);
    }
    #pragma unroll
    for (int o = 16; o; o >>= 1) m = fmaxf(m, __shfl_xor_sync(0xffffffffu, m, o));

    // pass 2: exp + sum, stash unnormalized
    float s = 0.f;
    for (int j = lane; j < cnt; j += 32) {
        float v = g_s_src[g_src_csr[start + j]] + sd;
        v = (v > 0.f) ? v : 0.01f * v;
        float ex = __expf(v - m);
        g_alpha[start + j] = ex;
        s += ex;
    }
    #pragma unroll
    for (int o = 16; o; o >>= 1) s += __shfl_xor_sync(0xffffffffu, s, o);
    float inv = (cnt > 0) ? (1.0f / s) : 0.f;

    // pass 3: normalize
    for (int j = lane; j < cnt; j += 32)
        g_alpha[start + j] *= inv;
}

// ---------------- K7: per-dst weighted gather-accumulate of h_s ----------------
__global__ void k_aggregate(const float* __restrict__ hs) {
    int p = blockIdx.x;
    int t = threadIdx.x;                       // 0..127
    int start = g_off[p];
    int cnt   = g_off[p + 1] - start;

    __shared__ int   ss[128];
    __shared__ float ws[128];

    float4 acc = make_float4(0.f, 0.f, 0.f, 0.f);
    for (int base = 0; base < cnt; base += 128) {
        int j = base + t;
        if (j < cnt) {
            ss[t] = g_src_csr[start + j];      // coalesced
            ws[t] = g_alpha[start + j];        // coalesced
        }
        __syncthreads();
        int lim = min(128, cnt - base);
        #pragma unroll 8
        for (int q = 0; q < lim; q++) {
            float w = ws[q];
            const float4* row = (const float4*)(hs + (size_t)ss[q] * D_IN);
            float4 v = __ldg(row + t);
            acc.x += w * v.x;
            acc.y += w * v.y;
            acc.z += w * v.z;
            acc.w += w * v.w;
        }
        __syncthreads();
    }

    // write bf16 hi/lo split, streaming (don't evict h_s from L2)
    float vv[4] = {acc.x, acc.y, acc.z, acc.w};
    unsigned short hb[4], lb[4];
    #pragma unroll
    for (int i = 0; i < 4; i++) {
        __nv_bfloat16 hi = __float2bfloat16_rn(vv[i]);
        float r = vv[i] - __bfloat162float(hi);
        __nv_bfloat16 lo = __float2bfloat16_rn(r);
        hb[i] = bf_bits(hi);
        lb[i] = bf_bits(lo);
    }
    size_t obase = (size_t)p * D_IN + t * 4;
    unsigned h0 = (unsigned)hb[0] | ((unsigned)hb[1] << 16);
    unsigned h1 = (unsigned)hb[2] | ((unsigned)hb[3] << 16);
    unsigned l0 = (unsigned)lb[0] | ((unsigned)lb[1] << 16);
    unsigned l1 = (unsigned)lb[2] | ((unsigned)lb[3] << 16);
    asm volatile("st.global.cs.v2.u32 [%0], {%1,%2};" :: "l"(g_agg_hi + obase), "r"(h0), "r"(h1));
    asm volatile("st.global.cs.v2.u32 [%0], {%1,%2};" :: "l"(g_agg_lo + obase), "r"(l0), "r"(l1));
}

// ---------------- K8: out = agg @ W^T via bf16-split MMA + ldmatrix -------------
#define SMS 24   // smem row stride in bf16 (48B: 16B-aligned, conflict-free)

__device__ __forceinline__ void mma_bf16(float d[4],
                                         unsigned a0, unsigned a1, unsigned a2, unsigned a3,
                                         unsigned b0, unsigned b1) {
    asm volatile(
        "mma.sync.aligned.m16n8k16.row.col.f32.bf16.bf16.f32 "
        "{%0,%1,%2,%3}, {%4,%5,%6,%7}, {%8,%9}, {%0,%1,%2,%3};\n"
        : "+f"(d[0]), "+f"(d[1]), "+f"(d[2]), "+f"(d[3])
        : "r"(a0), "r"(a1), "r"(a2), "r"(a3), "r"(b0), "r"(b1));
}

__device__ __forceinline__ void ldsm4(unsigned& r0, unsigned& r1, unsigned& r2, unsigned& r3,
                                      unsigned addr) {
    asm volatile("ldmatrix.sync.aligned.m8n8.x4.shared.b16 {%0,%1,%2,%3}, [%4];"
                 : "=r"(r0), "=r"(r1), "=r"(r2), "=r"(r3) : "r"(addr));
}

__global__ void __launch_bounds__(256) k_gemm_mma(float* __restrict__ out) {
    __shared__ __align__(16) __nv_bfloat16 sAh[128 * SMS];
    __shared__ __align__(16) __nv_bfloat16 sAl[128 * SMS];
    __shared__ __align__(16) __nv_bfloat16 sBh[128 * SMS];
    __shared__ __align__(16) __nv_bfloat16 sBl[128 * SMS];

    const int bm = blockIdx.x * 128;
    const int bn = blockIdx.y * 128;
    const int tid  = threadIdx.x;
    const int lane = tid & 31;
    const int warp = tid >> 5;
    const int wm = (warp >> 1) * 32;   // 0,32,64,96
    const int wn = (warp & 1) * 64;    // 0,64
    const int g  = lane >> 2;          // 0..7
    const int tg = lane & 3;           // 0..3

    const int lrow = tid >> 1;
    const int lc8  = (tid & 1) * 8;

    const __nv_bfloat16* gAh = g_agg_hi + (size_t)(bm + lrow) * D_IN + lc8;
    const __nv_bfloat16* gAl = g_agg_lo + (size_t)(bm + lrow) * D_IN + lc8;
    const __nv_bfloat16* gBh = g_W_hi   + (size_t)(bn + lrow) * D_IN + lc8;
    const __nv_bfloat16* gBl = g_W_lo   + (size_t)(bn + lrow) * D_IN + lc8;

    float d[2][8][4];
    #pragma unroll
    for (int mt = 0; mt < 2; mt++)
        #pragma unroll
        for (int nt = 0; nt < 8; nt++)
            #pragma unroll
            for (int i = 0; i < 4; i++) d[mt][nt][i] = 0.f;

    uint4 rah = *(const uint4*)gAh;
    uint4 ral = *(const uint4*)gAl;
    uint4 rbh = *(const uint4*)gBh;
    uint4 rbl = *(const uint4*)gBl;

    const int sidx = lrow * SMS + lc8;

    // ldmatrix smem byte addresses (constant across k-iters; slab reused)
    const unsigned baseAh = (unsigned)__cvta_generic_to_shared(sAh);
    const unsigned baseAl = (unsigned)__cvta_generic_to_shared(sAl);
    const unsigned baseBh = (unsigned)__cvta_generic_to_shared(sBh);
    const unsigned baseBl = (unsigned)__cvta_generic_to_shared(sBl);

    // A: matrices {rows0-7 k0, rows8-15 k0, rows0-7 k16B, rows8-15 k16B}
    const int arow = (lane & 15);
    const int akb  = (lane >> 4) * 16;
    unsigned aAddr[2], aAddrL[2];
    #pragma unroll
    for (int mt = 0; mt < 2; mt++) {
        int r = wm + mt * 16 + arow;
        aAddr[mt]  = baseAh + r * (SMS * 2) + akb;
        aAddrL[mt] = baseAl + r * (SMS * 2) + akb;
    }
    // B: per ntp (pair of nt): {n0-7 k0, n0-7 k16B, n8-15 k0, n8-15 k16B}
    const int brow = (lane & 7) + ((lane >> 4) & 1) * 8;
    const int bkb  = ((lane >> 3) & 1) * 16;
    unsigned bAddr[4], bAddrL[4];
    #pragma unroll
    for (int ntp = 0; ntp < 4; ntp++) {
        int r = wn + ntp * 16 + brow;
        bAddr[ntp]  = baseBh + r * (SMS * 2) + bkb;
        bAddrL[ntp] = baseBl + r * (SMS * 2) + bkb;
    }

    for (int ks = 0; ks < D_IN / 16; ks++) {
        *(uint4*)(sAh + sidx) = rah;
        *(uint4*)(sAl + sidx) = ral;
        *(uint4*)(sBh + sidx) = rbh;
        *(uint4*)(sBl + sidx) = rbl;
        __syncthreads();

        if (ks < D_IN / 16 - 1) {
            int koff = (ks + 1) * 16;
            rah = *(const uint4*)(gAh + koff);
            ral = *(const uint4*)(gAl + koff);
            rbh = *(const uint4*)(gBh + koff);
            rbl = *(const uint4*)(gBl + koff);
        }

        unsigned ah[2][4], al[2][4];
        #pragma unroll
        for (int mt = 0; mt < 2; mt++) {
            ldsm4(ah[mt][0], ah[mt][1], ah[mt][2], ah[mt][3], aAddr[mt]);
            ldsm4(al[mt][0], al[mt][1], al[mt][2], al[mt][3], aAddrL[mt]);
        }
        unsigned bh[4][4], bl[4][4];
        #pragma unroll
        for (int ntp = 0; ntp < 4; ntp++) {
            ldsm4(bh[ntp][0], bh[ntp][1], bh[ntp][2], bh[ntp][3], bAddr[ntp]);
            ldsm4(bl[ntp][0], bl[ntp][1], bl[ntp][2], bl[ntp][3], bAddrL[ntp]);
        }

        #pragma unroll
        for (int nt = 0; nt < 8; nt++) {
            int ntp = nt >> 1;
            int o   = (nt & 1) * 2;
            unsigned bh0 = bh[ntp][o], bh1 = bh[ntp][o + 1];
            unsigned bl0 = bl[ntp][o], bl1 = bl[ntp][o + 1];
            #pragma unroll
            for (int mt = 0; mt < 2; mt++) {
                mma_bf16(d[mt][nt], ah[mt][0], ah[mt][1], ah[mt][2], ah[mt][3], bh0, bh1);
                mma_bf16(d[mt][nt], ah[mt][0], ah[mt][1], ah[mt][2], ah[mt][3], bl0, bl1);
                mma_bf16(d[mt][nt], al[mt][0], al[mt][1], al[mt][2], al[mt][3], bh0, bh1);
            }
        }
        __syncthreads();
    }

    #pragma unroll
    for (int mt = 0; mt < 2; mt++) {
        #pragma unroll
        for (int nt = 0; nt < 8; nt++) {
            int r0 = bm + wm + mt * 16 + g;
            int c  = bn + wn + nt * 8 + tg * 2;
            if (r0 < N_P) {
                float2 v0 = make_float2(d[mt][nt][0], d[mt][nt][1]);
                *(float2*)(out + (size_t)r0 * D_OUT + c) = v0;
            }
            if (r0 + 8 < N_P) {
                float2 v1 = make_float2(d[mt][nt][2], d[mt][nt][3]);
                *(float2*)(out + (size_t)(r0 + 8) * D_OUT + c) = v1;
            }
        }
    }
}

// ---------------- launch ----------------
extern "C" void kernel_launch(void* const* d_in, const int* in_sizes, int n_in,
                              void* d_out, int out_size) {
    const float* hs  = (const float*)d_in[0];
    const float* hp  = (const float*)d_in[1];
    const float* W   = (const float*)d_in[2];
    const float* aw  = (const float*)d_in[3];
    const int*   src = (const int*)d_in[4];
    const int*   dst = (const int*)d_in[5];
    float*       out = (float*)d_out;

    k_zero_cnt<<<(N_P + 255) / 256, 256>>>();
    k_fold_w<<<16, 32>>>(W, aw);
    k_convw<<<(D_OUT * D_IN) / 1024, 1024>>>(W);
    k_count<<<(EN + 255) / 256, 256>>>(dst);
    k_scores<<<((N_S + N_P) * 32 + 255) / 256, 256>>>(hs, hp);
    k_scan<<<1, 1024>>>();
    k_scatter<<<(EN + 255) / 256, 256>>>(src, dst);
    k_softmax<<<(N_P * 32 + 255) / 256, 256>>>();
    k_aggregate<<<N_P, 128>>>(hs);
    k_gemm_mma<<<dim3(M_PAD / 128, D_OUT / 128), 256>>>(out);
}

// round 4
// speedup vs baseline: 1.0132x; 1.0132x over previous
#include <cuda_runtime.h>
#include <cuda_bf16.h>
#include <math_constants.h>

#define N_S   50000
#define N_P   10000
#define EN    320000
#define D_IN  512
#define D_OUT 256
#define M_PAD 10112   // 79 * 128

// ---------------- scratch (static device globals; no allocation) ----------------
__device__ __align__(16) float g_w1[D_IN];
__device__ __align__(16) float g_w2[D_IN];
__device__ float g_s_src[N_S];
__device__ float g_s_dst[N_P];
__device__ int   g_cnt[N_P];
__device__ int   g_off[N_P + 1];
__device__ int   g_cur[N_P];
__device__ int   g_src_csr[EN];
__device__ float g_alpha[EN];
// aggregated h per dst, bf16 hi/lo split (rows >= N_P stay zero)
__device__ __align__(16) __nv_bfloat16 g_agg_hi[(size_t)M_PAD * D_IN];
__device__ __align__(16) __nv_bfloat16 g_agg_lo[(size_t)M_PAD * D_IN];
// W in bf16 hi/lo split
__device__ __align__(16) __nv_bfloat16 g_W_hi[(size_t)D_OUT * D_IN];
__device__ __align__(16) __nv_bfloat16 g_W_lo[(size_t)D_OUT * D_IN];

__device__ __forceinline__ unsigned short bf_bits(__nv_bfloat16 h) {
    return *reinterpret_cast<unsigned short*>(&h);
}

// ---------------- K0: zero per-dst edge counts ----------------
__global__ void k_zero_cnt() {
    int i = blockIdx.x * blockDim.x + threadIdx.x;
    if (i < N_P) g_cnt[i] = 0;
}

// ---------------- K1: fold attention vector through W ----------------
__global__ void k_fold_w(const float* __restrict__ W, const float* __restrict__ aw) {
    int k = blockIdx.x * 32 + threadIdx.x;   // 16 blocks x 32 threads
    float a1 = 0.f, a2 = 0.f;
    #pragma unroll 8
    for (int d = 0; d < D_OUT; d++) {
        float w = W[d * D_IN + k];
        a1 += w * aw[d];
        a2 += w * aw[D_OUT + d];
    }
    g_w1[k] = a1;
    g_w2[k] = a2;
}

// ---------------- K1b: split W into bf16 hi/lo ----------------
__global__ void k_convw(const float* __restrict__ W) {
    int i = blockIdx.x * blockDim.x + threadIdx.x;
    float v = W[i];
    __nv_bfloat16 hi = __float2bfloat16_rn(v);
    float r = v - __bfloat162float(hi);
    g_W_hi[i] = hi;
    g_W_lo[i] = __float2bfloat16_rn(r);
}

// ---------------- K2: per-node scalar scores (warp per row) ----------------
__global__ void k_scores(const float* __restrict__ hs, const float* __restrict__ hp) {
    int gw   = (blockIdx.x * blockDim.x + threadIdx.x) >> 5;
    int lane = threadIdx.x & 31;
    if (gw >= N_S + N_P) return;
    float acc = 0.f;
    if (gw < N_S) {
        const float4* row = (const float4*)(hs + (size_t)gw * D_IN);
        const float4* wv  = (const float4*)g_w1;
        #pragma unroll
        for (int i = lane; i < D_IN / 4; i += 32) {
            float4 a = __ldg(row + i);      // warm L2 with h_s for the aggregate
            float4 b = wv[i];
            acc += a.x * b.x + a.y * b.y + a.z * b.z + a.w * b.w;
        }
    } else {
        const float4* row = (const float4*)(hp + (size_t)(gw - N_S) * D_IN);
        const float4* wv  = (const float4*)g_w2;
        #pragma unroll
        for (int i = lane; i < D_IN / 4; i += 32) {
            float4 a = __ldcs(row + i);     // streaming: h_p never reused
            float4 b = wv[i];
            acc += a.x * b.x + a.y * b.y + a.z * b.z + a.w * b.w;
        }
    }
    #pragma unroll
    for (int o = 16; o; o >>= 1) acc += __shfl_xor_sync(0xffffffffu, acc, o);
    if (lane == 0) {
        if (gw < N_S) g_s_src[gw] = acc;
        else          g_s_dst[gw - N_S] = acc;
    }
}

// ---------------- K3: dst histogram ----------------
__global__ void k_count(const int* __restrict__ dst) {
    int e = blockIdx.x * blockDim.x + threadIdx.x;
    if (e >= EN) return;
    atomicAdd(&g_cnt[dst[e]], 1);
}

// ---------------- K4: exclusive scan of counts -> CSR offsets ----------------
__global__ void k_scan() {
    __shared__ int wsum[32];
    int t    = threadIdx.x;
    int lane = t & 31;
    int wid  = t >> 5;
    int base = t * 10;
    int incl_loc[10];
    int cnts[10];
    int tot = 0;
    if (t < 1000) {
        #pragma unroll
        for (int i = 0; i < 10; i++) {
            int c = g_cnt[base + i];
            cnts[i] = c;
            tot += c;
            incl_loc[i] = tot;
        }
    }
    int incl = tot;
    #pragma unroll
    for (int o = 1; o < 32; o <<= 1) {
        int v = __shfl_up_sync(0xffffffffu, incl, o);
        if (lane >= o) incl += v;
    }
    if (lane == 31) wsum[wid] = incl;
    __syncthreads();
    if (wid == 0) {
        int v = wsum[lane];
        #pragma unroll
        for (int o = 1; o < 32; o <<= 1) {
            int u = __shfl_up_sync(0xffffffffu, v, o);
            if (lane >= o) v += u;
        }
        wsum[lane] = v;
    }
    __syncthreads();
    int warpoff = (wid == 0) ? 0 : wsum[wid - 1];
    int texcl   = warpoff + incl - tot;
    if (t < 1000) {
        #pragma unroll
        for (int i = 0; i < 10; i++) {
            int iv = texcl + incl_loc[i];
            g_off[base + i + 1] = iv;
            g_cur[base + i]     = iv - cnts[i];
        }
    }
    if (t == 0) g_off[0] = 0;
}

// ---------------- K5: scatter src ids into CSR order ----------------
__global__ void k_scatter(const int* __restrict__ src, const int* __restrict__ dst) {
    int e = blockIdx.x * blockDim.x + threadIdx.x;
    if (e >= EN) return;
    int pos = atomicAdd(&g_cur[dst[e]], 1);
    g_src_csr[pos] = src[e];
}

// ---------------- K6: warp-per-dst softmax -> alpha in CSR order ----------------
__global__ void k_softmax() {
    int p    = (blockIdx.x * blockDim.x + threadIdx.x) >> 5;
    int lane = threadIdx.x & 31;
    if (p >= N_P) return;
    int start = g_off[p];
    int cnt   = g_off[p + 1] - start;
    float sd  = g_s_dst[p];

    float m = -CUDART_INF_F;
    for (int j = lane; j < cnt; j += 32) {
        float v = g_s_src[g_src_csr[start + j]] + sd;
        v = (v > 0.f) ? v : 0.01f * v;
        m = fmaxf(m, v);
    }
    #pragma unroll
    for (int o = 16; o; o >>= 1) m = fmaxf(m, __shfl_xor_sync(0xffffffffu, m, o));

    float s = 0.f;
    for (int j = lane; j < cnt; j += 32) {
        float v = g_s_src[g_src_csr[start + j]] + sd;
        v = (v > 0.f) ? v : 0.01f * v;
        float ex = __expf(v - m);
        g_alpha[start + j] = ex;
        s += ex;
    }
    #pragma unroll
    for (int o = 16; o; o >>= 1) s += __shfl_xor_sync(0xffffffffu, s, o);
    float inv = (cnt > 0) ? (1.0f / s) : 0.f;

    for (int j = lane; j < cnt; j += 32)
        g_alpha[start + j] *= inv;
}

// ---------------- K7: per-dst weighted gather-accumulate, ONE COLUMN HALF -------
// Two sequential launches (half=0, half=1) so the touched h_s working set per
// launch is 51 MB -> stays L2-resident; gather served at LTS cap, not DRAM.
__global__ void __launch_bounds__(64) k_aggregate_half(const float* __restrict__ hs, int half) {
    int p = blockIdx.x;
    int t = threadIdx.x;                       // 0..63
    int start = g_off[p];
    int cnt   = g_off[p + 1] - start;
    int coloff = half * (D_IN / 2) + t * 4;    // this thread's 4 columns

    __shared__ int   ss[64];
    __shared__ float ws[64];

    float4 acc = make_float4(0.f, 0.f, 0.f, 0.f);
    for (int base = 0; base < cnt; base += 64) {
        int j = base + t;
        if (j < cnt) {
            ss[t] = g_src_csr[start + j];      // coalesced
            ws[t] = g_alpha[start + j];        // coalesced
        }
        __syncthreads();
        int lim = min(64, cnt - base);
        #pragma unroll 8
        for (int q = 0; q < lim; q++) {
            float w = ws[q];
            const float4* row = (const float4*)(hs + (size_t)ss[q] * D_IN + coloff);
            float4 v = __ldg(row);
            acc.x += w * v.x;
            acc.y += w * v.y;
            acc.z += w * v.z;
            acc.w += w * v.w;
        }
        __syncthreads();
    }

    // bf16 hi/lo split, streaming stores (don't evict h_s from L2)
    float vv[4] = {acc.x, acc.y, acc.z, acc.w};
    unsigned short hb[4], lb[4];
    #pragma unroll
    for (int i = 0; i < 4; i++) {
        __nv_bfloat16 hi = __float2bfloat16_rn(vv[i]);
        float r = vv[i] - __bfloat162float(hi);
        __nv_bfloat16 lo = __float2bfloat16_rn(r);
        hb[i] = bf_bits(hi);
        lb[i] = bf_bits(lo);
    }
    size_t obase = (size_t)p * D_IN + coloff;
    unsigned h0 = (unsigned)hb[0] | ((unsigned)hb[1] << 16);
    unsigned h1 = (unsigned)hb[2] | ((unsigned)hb[3] << 16);
    unsigned l0 = (unsigned)lb[0] | ((unsigned)lb[1] << 16);
    unsigned l1 = (unsigned)lb[2] | ((unsigned)lb[3] << 16);
    asm volatile("st.global.cs.v2.u32 [%0], {%1,%2};" :: "l"(g_agg_hi + obase), "r"(h0), "r"(h1));
    asm volatile("st.global.cs.v2.u32 [%0], {%1,%2};" :: "l"(g_agg_lo + obase), "r"(l0), "r"(l1));
}

// ---------------- K8: out = agg @ W^T via bf16-split MMA + ldmatrix -------------
#define SMS 24   // smem row stride in bf16 (48B: 16B-aligned, conflict-free)

__device__ __forceinline__ void mma_bf16(float d[4],
                                         unsigned a0, unsigned a1, unsigned a2, unsigned a3,
                                         unsigned b0, unsigned b1) {
    asm volatile(
        "mma.sync.aligned.m16n8k16.row.col.f32.bf16.bf16.f32 "
        "{%0,%1,%2,%3}, {%4,%5,%6,%7}, {%8,%9}, {%0,%1,%2,%3};\n"
        : "+f"(d[0]), "+f"(d[1]), "+f"(d[2]), "+f"(d[3])
        : "r"(a0), "r"(a1), "r"(a2), "r"(a3), "r"(b0), "r"(b1));
}

__device__ __forceinline__ void ldsm4(unsigned& r0, unsigned& r1, unsigned& r2, unsigned& r3,
                                      unsigned addr) {
    asm volatile("ldmatrix.sync.aligned.m8n8.x4.shared.b16 {%0,%1,%2,%3}, [%4];"
                 : "=r"(r0), "=r"(r1), "=r"(r2), "=r"(r3) : "r"(addr));
}

__global__ void __launch_bounds__(256) k_gemm_mma(float* __restrict__ out) {
    __shared__ __align__(16) __nv_bfloat16 sAh[128 * SMS];
    __shared__ __align__(16) __nv_bfloat16 sAl[128 * SMS];
    __shared__ __align__(16) __nv_bfloat16 sBh[128 * SMS];
    __shared__ __align__(16) __nv_bfloat16 sBl[128 * SMS];

    const int bm = blockIdx.x * 128;
    const int bn = blockIdx.y * 128;
    const int tid  = threadIdx.x;
    const int lane = tid & 31;
    const int warp = tid >> 5;
    const int wm = (warp >> 1) * 32;
    const int wn = (warp & 1) * 64;
    const int g  = lane >> 2;
    const int tg = lane & 3;

    const int lrow = tid >> 1;
    const int lc8  = (tid & 1) * 8;

    const __nv_bfloat16* gAh = g_agg_hi + (size_t)(bm + lrow) * D_IN + lc8;
    const __nv_bfloat16* gAl = g_agg_lo + (size_t)(bm + lrow) * D_IN + lc8;
    const __nv_bfloat16* gBh = g_W_hi   + (size_t)(bn + lrow) * D_IN + lc8;
    const __nv_bfloat16* gBl = g_W_lo   + (size_t)(bn + lrow) * D_IN + lc8;

    float d[2][8][4];
    #pragma unroll
    for (int mt = 0; mt < 2; mt++)
        #pragma unroll
        for (int nt = 0; nt < 8; nt++)
            #pragma unroll
            for (int i = 0; i < 4; i++) d[mt][nt][i] = 0.f;

    uint4 rah = *(const uint4*)gAh;
    uint4 ral = *(const uint4*)gAl;
    uint4 rbh = *(const uint4*)gBh;
    uint4 rbl = *(const uint4*)gBl;

    const int sidx = lrow * SMS + lc8;

    const unsigned baseAh = (unsigned)__cvta_generic_to_shared(sAh);
    const unsigned baseAl = (unsigned)__cvta_generic_to_shared(sAl);
    const unsigned baseBh = (unsigned)__cvta_generic_to_shared(sBh);
    const unsigned baseBl = (unsigned)__cvta_generic_to_shared(sBl);

    const int arow = (lane & 15);
    const int akb  = (lane >> 4) * 16;
    unsigned aAddr[2], aAddrL[2];
    #pragma unroll
    for (int mt = 0; mt < 2; mt++) {
        int r = wm + mt * 16 + arow;
        aAddr[mt]  = baseAh + r * (SMS * 2) + akb;
        aAddrL[mt] = baseAl + r * (SMS * 2) + akb;
    }
    const int brow = (lane & 7) + ((lane >> 4) & 1) * 8;
    const int bkb  = ((lane >> 3) & 1) * 16;
    unsigned bAddr[4], bAddrL[4];
    #pragma unroll
    for (int ntp = 0; ntp < 4; ntp++) {
        int r = wn + ntp * 16 + brow;
        bAddr[ntp]  = baseBh + r * (SMS * 2) + bkb;
        bAddrL[ntp] = baseBl + r * (SMS * 2) + bkb;
    }

    for (int ks = 0; ks < D_IN / 16; ks++) {
        *(uint4*)(sAh + sidx) = rah;
        *(uint4*)(sAl + sidx) = ral;
        *(uint4*)(sBh + sidx) = rbh;
        *(uint4*)(sBl + sidx) = rbl;
        __syncthreads();

        if (ks < D_IN / 16 - 1) {
            int koff = (ks + 1) * 16;
            rah = *(const uint4*)(gAh + koff);
            ral = *(const uint4*)(gAl + koff);
            rbh = *(const uint4*)(gBh + koff);
            rbl = *(const uint4*)(gBl + koff);
        }

        unsigned ah[2][4], al[2][4];
        #pragma unroll
        for (int mt = 0; mt < 2; mt++) {
            ldsm4(ah[mt][0], ah[mt][1], ah[mt][2], ah[mt][3], aAddr[mt]);
            ldsm4(al[mt][0], al[mt][1], al[mt][2], al[mt][3], aAddrL[mt]);
        }
        unsigned bh[4][4], bl[4][4];
        #pragma unroll
        for (int ntp = 0; ntp < 4; ntp++) {
            ldsm4(bh[ntp][0], bh[ntp][1], bh[ntp][2], bh[ntp][3], bAddr[ntp]);
            ldsm4(bl[ntp][0], bl[ntp][1], bl[ntp][2], bl[ntp][3], bAddrL[ntp]);
        }

        #pragma unroll
        for (int nt = 0; nt < 8; nt++) {
            int ntp = nt >> 1;
            int o   = (nt & 1) * 2;
            unsigned bh0 = bh[ntp][o], bh1 = bh[ntp][o + 1];
            unsigned bl0 = bl[ntp][o], bl1 = bl[ntp][o + 1];
            #pragma unroll
            for (int mt = 0; mt < 2; mt++) {
                mma_bf16(d[mt][nt], ah[mt][0], ah[mt][1], ah[mt][2], ah[mt][3], bh0, bh1);
                mma_bf16(d[mt][nt], ah[mt][0], ah[mt][1], ah[mt][2], ah[mt][3], bl0, bl1);
                mma_bf16(d[mt][nt], al[mt][0], al[mt][1], al[mt][2], al[mt][3], bh0, bh1);
            }
        }
        __syncthreads();
    }

    #pragma unroll
    for (int mt = 0; mt < 2; mt++) {
        #pragma unroll
        for (int nt = 0; nt < 8; nt++) {
            int r0 = bm + wm + mt * 16 + g;
            int c  = bn + wn + nt * 8 + tg * 2;
            if (r0 < N_P) {
                float2 v0 = make_float2(d[mt][nt][0], d[mt][nt][1]);
                *(float2*)(out + (size_t)r0 * D_OUT + c) = v0;
            }
            if (r0 + 8 < N_P) {
                float2 v1 = make_float2(d[mt][nt][2], d[mt][nt][3]);
                *(float2*)(out + (size_t)(r0 + 8) * D_OUT + c) = v1;
            }
        }
    }
}

// ---------------- launch ----------------
extern "C" void kernel_launch(void* const* d_in, const int* in_sizes, int n_in,
                              void* d_out, int out_size) {
    const float* hs  = (const float*)d_in[0];
    const float* hp  = (const float*)d_in[1];
    const float* W   = (const float*)d_in[2];
    const float* aw  = (const float*)d_in[3];
    const int*   src = (const int*)d_in[4];
    const int*   dst = (const int*)d_in[5];
    float*       out = (float*)d_out;

    k_zero_cnt<<<(N_P + 255) / 256, 256>>>();
    k_fold_w<<<16, 32>>>(W, aw);
    k_convw<<<(D_OUT * D_IN) / 1024, 1024>>>(W);
    k_count<<<(EN + 255) / 256, 256>>>(dst);
    k_scores<<<((N_S + N_P) * 32 + 255) / 256, 256>>>(hs, hp);
    k_scan<<<1, 1024>>>();
    k_scatter<<<(EN + 255) / 256, 256>>>(src, dst);
    k_softmax<<<(N_P * 32 + 255) / 256, 256>>>();
    k_aggregate_half<<<N_P, 64>>>(hs, 0);
    k_aggregate_half<<<N_P, 64>>>(hs, 1);
    k_gemm_mma<<<dim3(M_PAD / 128, D_OUT / 128), 256>>>(out);
}

// round 5
// speedup vs baseline: 1.1687x; 1.1534x over previous
#include <cuda_runtime.h>
#include <cuda_bf16.h>
#include <math_constants.h>

#define N_S   50000
#define N_P   10000
#define EN    320000
#define D_IN  512
#define D_OUT 256
#define M_PAD 10112   // 79 * 128
#define ROW_SPLIT 5120  // 40 gemm M-tiles

// ---------------- scratch (static device globals; no allocation) ----------------
__device__ __align__(16) float g_w1[D_IN];
__device__ __align__(16) float g_w2[D_IN];
__device__ float g_s_src[N_S];
__device__ float g_s_dst[N_P];
__device__ int   g_cnt[N_P];
__device__ int   g_off[N_P + 1];
__device__ int   g_cur[N_P];
__device__ int   g_src_csr[EN];
__device__ float g_alpha[EN];
// aggregated h per dst, bf16 hi/lo split (rows >= N_P stay zero)
__device__ __align__(16) __nv_bfloat16 g_agg_hi[(size_t)M_PAD * D_IN];
__device__ __align__(16) __nv_bfloat16 g_agg_lo[(size_t)M_PAD * D_IN];
// W in bf16 hi/lo split
__device__ __align__(16) __nv_bfloat16 g_W_hi[(size_t)D_OUT * D_IN];
__device__ __align__(16) __nv_bfloat16 g_W_lo[(size_t)D_OUT * D_IN];

__device__ __forceinline__ unsigned short bf_bits(__nv_bfloat16 h) {
    return *reinterpret_cast<unsigned short*>(&h);
}

// ---------------- K0: zero per-dst edge counts ----------------
__global__ void k_zero_cnt() {
    int i = blockIdx.x * blockDim.x + threadIdx.x;
    if (i < N_P) g_cnt[i] = 0;
}

// ---------------- K1: fold attention vector through W ----------------
__global__ void k_fold_w(const float* __restrict__ W, const float* __restrict__ aw) {
    int k = blockIdx.x * 32 + threadIdx.x;   // 16 blocks x 32 threads
    float a1 = 0.f, a2 = 0.f;
    #pragma unroll 8
    for (int d = 0; d < D_OUT; d++) {
        float w = W[d * D_IN + k];
        a1 += w * aw[d];
        a2 += w * aw[D_OUT + d];
    }
    g_w1[k] = a1;
    g_w2[k] = a2;
}

// ---------------- K1b: split W into bf16 hi/lo ----------------
__global__ void k_convw(const float* __restrict__ W) {
    int i = blockIdx.x * blockDim.x + threadIdx.x;
    float v = W[i];
    __nv_bfloat16 hi = __float2bfloat16_rn(v);
    float r = v - __bfloat162float(hi);
    g_W_hi[i] = hi;
    g_W_lo[i] = __float2bfloat16_rn(r);
}

// ---------------- K2: per-node scalar scores (warp per row) ----------------
__global__ void k_scores(const float* __restrict__ hs, const float* __restrict__ hp) {
    int gw   = (blockIdx.x * blockDim.x + threadIdx.x) >> 5;
    int lane = threadIdx.x & 31;
    if (gw >= N_S + N_P) return;
    float acc = 0.f;
    if (gw < N_S) {
        const float4* row = (const float4*)(hs + (size_t)gw * D_IN);
        const float4* wv  = (const float4*)g_w1;
        #pragma unroll
        for (int i = lane; i < D_IN / 4; i += 32) {
            float4 a = __ldg(row + i);
            float4 b = wv[i];
            acc += a.x * b.x + a.y * b.y + a.z * b.z + a.w * b.w;
        }
    } else {
        const float4* row = (const float4*)(hp + (size_t)(gw - N_S) * D_IN);
        const float4* wv  = (const float4*)g_w2;
        #pragma unroll
        for (int i = lane; i < D_IN / 4; i += 32) {
            float4 a = __ldcs(row + i);     // streaming: h_p never reused
            float4 b = wv[i];
            acc += a.x * b.x + a.y * b.y + a.z * b.z + a.w * b.w;
        }
    }
    #pragma unroll
    for (int o = 16; o; o >>= 1) acc += __shfl_xor_sync(0xffffffffu, acc, o);
    if (lane == 0) {
        if (gw < N_S) g_s_src[gw] = acc;
        else          g_s_dst[gw - N_S] = acc;
    }
}

// ---------------- K3: dst histogram (4 edges per thread) ----------------
__global__ void k_count(const int4* __restrict__ dst4) {
    int i = blockIdx.x * blockDim.x + threadIdx.x;
    if (i >= EN / 4) return;
    int4 d = dst4[i];
    atomicAdd(&g_cnt[d.x], 1);
    atomicAdd(&g_cnt[d.y], 1);
    atomicAdd(&g_cnt[d.z], 1);
    atomicAdd(&g_cnt[d.w], 1);
}

// ---------------- K4: exclusive scan of counts -> CSR offsets ----------------
__global__ void k_scan() {
    __shared__ int wsum[32];
    int t    = threadIdx.x;
    int lane = t & 31;
    int wid  = t >> 5;
    int base = t * 10;
    int incl_loc[10];
    int cnts[10];
    int tot = 0;
    if (t < 1000) {
        #pragma unroll
        for (int i = 0; i < 10; i++) {
            int c = g_cnt[base + i];
            cnts[i] = c;
            tot += c;
            incl_loc[i] = tot;
        }
    }
    int incl = tot;
    #pragma unroll
    for (int o = 1; o < 32; o <<= 1) {
        int v = __shfl_up_sync(0xffffffffu, incl, o);
        if (lane >= o) incl += v;
    }
    if (lane == 31) wsum[wid] = incl;
    __syncthreads();
    if (wid == 0) {
        int v = wsum[lane];
        #pragma unroll
        for (int o = 1; o < 32; o <<= 1) {
            int u = __shfl_up_sync(0xffffffffu, v, o);
            if (lane >= o) v += u;
        }
        wsum[lane] = v;
    }
    __syncthreads();
    int warpoff = (wid == 0) ? 0 : wsum[wid - 1];
    int texcl   = warpoff + incl - tot;
    if (t < 1000) {
        #pragma unroll
        for (int i = 0; i < 10; i++) {
            int iv = texcl + incl_loc[i];
            g_off[base + i + 1] = iv;
            g_cur[base + i]     = iv - cnts[i];
        }
    }
    if (t == 0) g_off[0] = 0;
}

// ---------------- K5: scatter src ids into CSR order (4 edges per thread) -------
__global__ void k_scatter(const int4* __restrict__ src4, const int4* __restrict__ dst4) {
    int i = blockIdx.x * blockDim.x + threadIdx.x;
    if (i >= EN / 4) return;
    int4 s = src4[i];
    int4 d = dst4[i];
    int p0 = atomicAdd(&g_cur[d.x], 1); g_src_csr[p0] = s.x;
    int p1 = atomicAdd(&g_cur[d.y], 1); g_src_csr[p1] = s.y;
    int p2 = atomicAdd(&g_cur[d.z], 1); g_src_csr[p2] = s.z;
    int p3 = atomicAdd(&g_cur[d.w], 1); g_src_csr[p3] = s.w;
}

// ---------------- K6: warp-per-dst softmax -> alpha in CSR order ----------------
__global__ void k_softmax() {
    int p    = (blockIdx.x * blockDim.x + threadIdx.x) >> 5;
    int lane = threadIdx.x & 31;
    if (p >= N_P) return;
    int start = g_off[p];
    int cnt   = g_off[p + 1] - start;
    float sd  = g_s_dst[p];

    float m = -CUDART_INF_F;
    for (int j = lane; j < cnt; j += 32) {
        float v = g_s_src[g_src_csr[start + j]] + sd;
        v = (v > 0.f) ? v : 0.01f * v;
        m = fmaxf(m, v);
    }
    #pragma unroll
    for (int o = 16; o; o >>= 1) m = fmaxf(m, __shfl_xor_sync(0xffffffffu, m, o));

    float s = 0.f;
    for (int j = lane; j < cnt; j += 32) {
        float v = g_s_src[g_src_csr[start + j]] + sd;
        v = (v > 0.f) ? v : 0.01f * v;
        float ex = __expf(v - m);
        g_alpha[start + j] = ex;
        s += ex;
    }
    #pragma unroll
    for (int o = 16; o; o >>= 1) s += __shfl_xor_sync(0xffffffffu, s, o);
    float inv = (cnt > 0) ? (1.0f / s) : 0.f;

    for (int j = lane; j < cnt; j += 32)
        g_alpha[start + j] *= inv;
}

// ---------------- K7: per-dst weighted gather-accumulate (full 512-col row) -----
__global__ void __launch_bounds__(128) k_aggregate(const float* __restrict__ hs, int pBase) {
    int p = pBase + blockIdx.x;
    int t = threadIdx.x;                       // 0..127
    int start = g_off[p];
    int cnt   = g_off[p + 1] - start;

    __shared__ int   ss[128];
    __shared__ float ws[128];

    float4 acc = make_float4(0.f, 0.f, 0.f, 0.f);
    for (int base = 0; base < cnt; base += 128) {
        int j = base + t;
        if (j < cnt) {
            ss[t] = g_src_csr[start + j];      // coalesced
            ws[t] = g_alpha[start + j];        // coalesced
        }
        __syncthreads();
        int lim = min(128, cnt - base);
        #pragma unroll 8
        for (int q = 0; q < lim; q++) {
            float w = ws[q];
            const float4* row = (const float4*)(hs + (size_t)ss[q] * D_IN);
            float4 v = __ldg(row + t);
            acc.x += w * v.x;
            acc.y += w * v.y;
            acc.z += w * v.z;
            acc.w += w * v.w;
        }
        __syncthreads();
    }

    float vv[4] = {acc.x, acc.y, acc.z, acc.w};
    unsigned short hb[4], lb[4];
    #pragma unroll
    for (int i = 0; i < 4; i++) {
        __nv_bfloat16 hi = __float2bfloat16_rn(vv[i]);
        float r = vv[i] - __bfloat162float(hi);
        __nv_bfloat16 lo = __float2bfloat16_rn(r);
        hb[i] = bf_bits(hi);
        lb[i] = bf_bits(lo);
    }
    size_t obase = (size_t)p * D_IN + t * 4;
    unsigned h0 = (unsigned)hb[0] | ((unsigned)hb[1] << 16);
    unsigned h1 = (unsigned)hb[2] | ((unsigned)hb[3] << 16);
    unsigned l0 = (unsigned)lb[0] | ((unsigned)lb[1] << 16);
    unsigned l1 = (unsigned)lb[2] | ((unsigned)lb[3] << 16);
    asm volatile("st.global.cs.v2.u32 [%0], {%1,%2};" :: "l"(g_agg_hi + obase), "r"(h0), "r"(h1));
    asm volatile("st.global.cs.v2.u32 [%0], {%1,%2};" :: "l"(g_agg_lo + obase), "r"(l0), "r"(l1));
}

// ---------------- K8: out = agg @ W^T via bf16-split MMA + ldmatrix -------------
#define SMS 24   // smem row stride in bf16 (48B: 16B-aligned, conflict-free)

__device__ __forceinline__ void mma_bf16(float d[4],
                                         unsigned a0, unsigned a1, unsigned a2, unsigned a3,
                                         unsigned b0, unsigned b1) {
    asm volatile(
        "mma.sync.aligned.m16n8k16.row.col.f32.bf16.bf16.f32 "
        "{%0,%1,%2,%3}, {%4,%5,%6,%7}, {%8,%9}, {%0,%1,%2,%3};\n"
        : "+f"(d[0]), "+f"(d[1]), "+f"(d[2]), "+f"(d[3])
        : "r"(a0), "r"(a1), "r"(a2), "r"(a3), "r"(b0), "r"(b1));
}

__device__ __forceinline__ void ldsm4(unsigned& r0, unsigned& r1, unsigned& r2, unsigned& r3,
                                      unsigned addr) {
    asm volatile("ldmatrix.sync.aligned.m8n8.x4.shared.b16 {%0,%1,%2,%3}, [%4];"
                 : "=r"(r0), "=r"(r1), "=r"(r2), "=r"(r3) : "r"(addr));
}

__global__ void __launch_bounds__(256) k_gemm_mma(float* __restrict__ out, int bmBase) {
    __shared__ __align__(16) __nv_bfloat16 sAh[128 * SMS];
    __shared__ __align__(16) __nv_bfloat16 sAl[128 * SMS];
    __shared__ __align__(16) __nv_bfloat16 sBh[128 * SMS];
    __shared__ __align__(16) __nv_bfloat16 sBl[128 * SMS];

    const int bm = (blockIdx.x + bmBase) * 128;
    const int bn = blockIdx.y * 128;
    const int tid  = threadIdx.x;
    const int lane = tid & 31;
    const int warp = tid >> 5;
    const int wm = (warp >> 1) * 32;
    const int wn = (warp & 1) * 64;
    const int g  = lane >> 2;
    const int tg = lane & 3;

    const int lrow = tid >> 1;
    const int lc8  = (tid & 1) * 8;

    const __nv_bfloat16* gAh = g_agg_hi + (size_t)(bm + lrow) * D_IN + lc8;
    const __nv_bfloat16* gAl = g_agg_lo + (size_t)(bm + lrow) * D_IN + lc8;
    const __nv_bfloat16* gBh = g_W_hi   + (size_t)(bn + lrow) * D_IN + lc8;
    const __nv_bfloat16* gBl = g_W_lo   + (size_t)(bn + lrow) * D_IN + lc8;

    float d[2][8][4];
    #pragma unroll
    for (int mt = 0; mt < 2; mt++)
        #pragma unroll
        for (int nt = 0; nt < 8; nt++)
            #pragma unroll
            for (int i = 0; i < 4; i++) d[mt][nt][i] = 0.f;

    uint4 rah = *(const uint4*)gAh;
    uint4 ral = *(const uint4*)gAl;
    uint4 rbh = *(const uint4*)gBh;
    uint4 rbl = *(const uint4*)gBl;

    const int sidx = lrow * SMS + lc8;

    const unsigned baseAh = (unsigned)__cvta_generic_to_shared(sAh);
    const unsigned baseAl = (unsigned)__cvta_generic_to_shared(sAl);
    const unsigned baseBh = (unsigned)__cvta_generic_to_shared(sBh);
    const unsigned baseBl = (unsigned)__cvta_generic_to_shared(sBl);

    const int arow = (lane & 15);
    const int akb  = (lane >> 4) * 16;
    unsigned aAddr[2], aAddrL[2];
    #pragma unroll
    for (int mt = 0; mt < 2; mt++) {
        int r = wm + mt * 16 + arow;
        aAddr[mt]  = baseAh + r * (SMS * 2) + akb;
        aAddrL[mt] = baseAl + r * (SMS * 2) + akb;
    }
    const int brow = (lane & 7) + ((lane >> 4) & 1) * 8;
    const int bkb  = ((lane >> 3) & 1) * 16;
    unsigned bAddr[4], bAddrL[4];
    #pragma unroll
    for (int ntp = 0; ntp < 4; ntp++) {
        int r = wn + ntp * 16 + brow;
        bAddr[ntp]  = baseBh + r * (SMS * 2) + bkb;
        bAddrL[ntp] = baseBl + r * (SMS * 2) + bkb;
    }

    for (int ks = 0; ks < D_IN / 16; ks++) {
        *(uint4*)(sAh + sidx) = rah;
        *(uint4*)(sAl + sidx) = ral;
        *(uint4*)(sBh + sidx) = rbh;
        *(uint4*)(sBl + sidx) = rbl;
        __syncthreads();

        if (ks < D_IN / 16 - 1) {
            int koff = (ks + 1) * 16;
            rah = *(const uint4*)(gAh + koff);
            ral = *(const uint4*)(gAl + koff);
            rbh = *(const uint4*)(gBh + koff);
            rbl = *(const uint4*)(gBl + koff);
        }

        unsigned ah[2][4], al[2][4];
        #pragma unroll
        for (int mt = 0; mt < 2; mt++) {
            ldsm4(ah[mt][0], ah[mt][1], ah[mt][2], ah[mt][3], aAddr[mt]);
            ldsm4(al[mt][0], al[mt][1], al[mt][2], al[mt][3], aAddrL[mt]);
        }
        unsigned bh[4][4], bl[4][4];
        #pragma unroll
        for (int ntp = 0; ntp < 4; ntp++) {
            ldsm4(bh[ntp][0], bh[ntp][1], bh[ntp][2], bh[ntp][3], bAddr[ntp]);
            ldsm4(bl[ntp][0], bl[ntp][1], bl[ntp][2], bl[ntp][3], bAddrL[ntp]);
        }

        #pragma unroll
        for (int nt = 0; nt < 8; nt++) {
            int ntp = nt >> 1;
            int o   = (nt & 1) * 2;
            unsigned bh0 = bh[ntp][o], bh1 = bh[ntp][o + 1];
            unsigned bl0 = bl[ntp][o], bl1 = bl[ntp][o + 1];
            #pragma unroll
            for (int mt = 0; mt < 2; mt++) {
                mma_bf16(d[mt][nt], ah[mt][0], ah[mt][1], ah[mt][2], ah[mt][3], bh0, bh1);
                mma_bf16(d[mt][nt], ah[mt][0], ah[mt][1], ah[mt][2], ah[mt][3], bl0, bl1);
                mma_bf16(d[mt][nt], al[mt][0], al[mt][1], al[mt][2], al[mt][3], bh0, bh1);
            }
        }
        __syncthreads();
    }

    #pragma unroll
    for (int mt = 0; mt < 2; mt++) {
        #pragma unroll
        for (int nt = 0; nt < 8; nt++) {
            int r0 = bm + wm + mt * 16 + g;
            int c  = bn + wn + nt * 8 + tg * 2;
            if (r0 < N_P) {
                float2 v0 = make_float2(d[mt][nt][0], d[mt][nt][1]);
                *(float2*)(out + (size_t)r0 * D_OUT + c) = v0;
            }
            if (r0 + 8 < N_P) {
                float2 v1 = make_float2(d[mt][nt][2], d[mt][nt][3]);
                *(float2*)(out + (size_t)(r0 + 8) * D_OUT + c) = v1;
            }
        }
    }
}

// ---------------- stream/event context (created at load, before harness checkpoints)
struct HxCtx {
    cudaStream_t sB, sC;
    cudaEvent_t evRoot, evB, evG1, evG2, evC;
    HxCtx() {
        cudaStreamCreateWithFlags(&sB, cudaStreamNonBlocking);
        cudaStreamCreateWithFlags(&sC, cudaStreamNonBlocking);
        cudaEventCreateWithFlags(&evRoot, cudaEventDisableTiming);
        cudaEventCreateWithFlags(&evB,    cudaEventDisableTiming);
        cudaEventCreateWithFlags(&evG1,   cudaEventDisableTiming);
        cudaEventCreateWithFlags(&evG2,   cudaEventDisableTiming);
        cudaEventCreateWithFlags(&evC,    cudaEventDisableTiming);
    }
};
static HxCtx hx;

// ---------------- launch ----------------
extern "C" void kernel_launch(void* const* d_in, const int* in_sizes, int n_in,
                              void* d_out, int out_size) {
    const float* hs  = (const float*)d_in[0];
    const float* hp  = (const float*)d_in[1];
    const float* W   = (const float*)d_in[2];
    const float* aw  = (const float*)d_in[3];
    const int*   src = (const int*)d_in[4];
    const int*   dst = (const int*)d_in[5];
    float*       out = (float*)d_out;

    // fork
    cudaEventRecord(hx.evRoot, 0);
    cudaStreamWaitEvent(hx.sB, hx.evRoot, 0);
    cudaStreamWaitEvent(hx.sC, hx.evRoot, 0);

    // chain B (edge structure): zero -> count -> scan -> scatter
    k_zero_cnt<<<(N_P + 255) / 256, 256, 0, hx.sB>>>();
    k_count<<<(EN / 4 + 255) / 256, 256, 0, hx.sB>>>((const int4*)dst);
    k_scan<<<1, 1024, 0, hx.sB>>>();
    k_scatter<<<(EN / 4 + 255) / 256, 256, 0, hx.sB>>>((const int4*)src, (const int4*)dst);
    cudaEventRecord(hx.evB, hx.sB);

    // chain C (weights): convw, later gemm
    k_convw<<<(D_OUT * D_IN) / 1024, 1024, 0, hx.sC>>>(W);

    // chain 0 (scores): fold -> scores, then join B -> softmax -> aggregate halves
    k_fold_w<<<16, 32>>>(W, aw);
    k_scores<<<((N_S + N_P) * 32 + 255) / 256, 256>>>(hs, hp);
    cudaStreamWaitEvent(0, hx.evB, 0);
    k_softmax<<<(N_P * 32 + 255) / 256, 256>>>();
    k_aggregate<<<ROW_SPLIT, 128>>>(hs, 0);
    cudaEventRecord(hx.evG1, 0);
    k_aggregate<<<N_P - ROW_SPLIT, 128>>>(hs, ROW_SPLIT);
    cudaEventRecord(hx.evG2, 0);

    // gemm pipelined on chain C (overlaps second aggregate half)
    cudaStreamWaitEvent(hx.sC, hx.evG1, 0);
    k_gemm_mma<<<dim3(ROW_SPLIT / 128, D_OUT / 128), 256, 0, hx.sC>>>(out, 0);
    cudaStreamWaitEvent(hx.sC, hx.evG2, 0);
    k_gemm_mma<<<dim3(M_PAD / 128 - ROW_SPLIT / 128, D_OUT / 128), 256, 0, hx.sC>>>(out, ROW_SPLIT / 128);
    cudaEventRecord(hx.evC, hx.sC);

    // join everything back to the capture stream
    cudaStreamWaitEvent(0, hx.evC, 0);
}